// round 10
// baseline (speedup 1.0000x reference)
#include <cuda_runtime.h>
#include <math.h>

#define WW 1024
#define HH 1024
#define BB 8
#define HWSZ (1024*1024)
#define EPSF 1e-10f

// Global accumulators (zeroed each launch by zero_acc kernel).
// Layout: lp[3], lpat[3], I[3*8], Up[3*8], T[8]
__device__ double g_lp[3];
__device__ double g_lpat[3];
__device__ double g_I[24];
__device__ double g_Up[24];
__device__ double g_T[8];

__global__ void zero_acc_kernel() {
    int i = threadIdx.x;
    if (i < 3)  { g_lp[i] = 0.0; g_lpat[i] = 0.0; }
    if (i < 24) { g_I[i] = 0.0; g_Up[i] = 0.0; }
    if (i < 8)  { g_T[i] = 0.0; }
}

// Main fused kernel.
// Grid: (W/256, H/8, B). Each thread handles 8 vertically adjacent pixels at
// one (b, w) column. The 7x7 circular conv over `target` (zero padded) is
// computed via shared row partial sums:
//   circle row half-widths: dy=0 -> 7-wide (S7), |dy|=1,2 -> 5-wide (S5),
//   |dy|=3 -> 1-wide (S1). 29 taps total, each weight 1/29.
__global__ __launch_bounds__(256)
void combine_loss_main(const float* __restrict__ pred,
                       const float* __restrict__ diss,
                       const int*   __restrict__ target)
{
    const int b  = blockIdx.z;
    const int w  = blockIdx.x * 256 + threadIdx.x;
    const int h0 = blockIdx.y * 8;

    const int* __restrict__ tb = target + (long)b * HWSZ;

    // Column validity for offsets dc = -3..3
    bool cok[7];
#pragma unroll
    for (int d = 0; d < 7; d++) {
        int c = w + d - 3;
        cok[d] = ((unsigned)c < (unsigned)WW);
    }

    // Row partial sums for rows r = h0-3 .. h0+10 (array index a = r-(h0-3))
    int S1[14];
    int S5[14];
    int S7[14];     // only a = 3..10 used
    int center[8];  // t value at (h0+j, w)

#pragma unroll
    for (int a = 0; a < 14; a++) {
        const int r = h0 - 3 + a;
        const bool rok = ((unsigned)r < (unsigned)HH);
        // Width needed for this row:
        //   a==0 || a==13          -> S1 only  (load v[3])
        //   a in {1,2,11,12}       -> S5       (load v[1..5])
        //   a in 3..10             -> S7       (load v[0..6])
        const int lo = (a >= 3 && a <= 10) ? 0 : ((a == 0 || a == 13) ? 3 : 1);
        const int hi = 6 - lo;
        int v[7];
#pragma unroll
        for (int d = 0; d < 7; d++) {
            v[d] = 0;
            if (d >= lo && d <= hi) {
                if (rok & cok[d]) v[d] = tb[(long)r * WW + (w - 3 + d)];
            }
        }
        const int s1 = v[3];
        const int s5 = v[1] + v[2] + v[3] + v[4] + v[5];
        const int s7 = s5 + v[0] + v[6];
        S1[a] = s1;
        S5[a] = s5;
        S7[a] = s7;
        if (a >= 3 && a <= 10) center[a - 3] = v[3];
    }

    // Per-thread accumulators (float; block sums stay small enough)
    float a_lp0 = 0.f, a_lp1 = 0.f, a_lp2 = 0.f;
    float a_ea0 = 0.f, a_ea1 = 0.f, a_ea2 = 0.f;
    float a_I0 = 0.f, a_I1 = 0.f, a_I2 = 0.f;
    float a_U0 = 0.f, a_U1 = 0.f, a_U2 = 0.f;
    float a_T  = 0.f;

    const long pixbase = (long)h0 * WW + w;
    const float* __restrict__ p0base = pred + ((long)(0 * BB + b) * 2) * HWSZ;
    const float* __restrict__ p1base = pred + ((long)(1 * BB + b) * 2) * HWSZ;
    const float* __restrict__ dbase  = diss + ((long)b * 2) * HWSZ;

#pragma unroll
    for (int j = 0; j < 8; j++) {
        const int a = j + 3;
        const int cnt = S7[a]
                      + S5[a - 1] + S5[a + 1] + S5[a - 2] + S5[a + 2]
                      + S1[a - 3] + S1[a + 3];
        const int   t  = center[j];
        const float tf = (float)t;
        const float at = fabsf(tf - (float)cnt * (1.0f / 29.0f));

        const long pix = pixbase + (long)j * WW;

        // prob 0: softmax(predictions[0]) — sigmoid form
        {
            const float x0 = p0base[pix];
            const float x1 = p0base[pix + HWSZ];
            const float e  = __expf(x0 - x1);
            const float p1 = __fdividef(1.0f, 1.0f + e);
            const float pt = t ? p1 : e * p1;
            const float lp = __logf(pt + EPSF);
            a_lp0 -= lp;
            a_ea0 -= lp * at;
            a_I0  += p1 * tf;
            a_U0  += p1;
        }
        // prob 1: softmax(predictions[1])
        {
            const float x0 = p1base[pix];
            const float x1 = p1base[pix + HWSZ];
            const float e  = __expf(x0 - x1);
            const float p1 = __fdividef(1.0f, 1.0f + e);
            const float pt = t ? p1 : e * p1;
            const float lp = __logf(pt + EPSF);
            a_lp1 -= lp;
            a_ea1 -= lp * at;
            a_I1  += p1 * tf;
            a_U1  += p1;
        }
        // prob 2: Diss[0] used directly
        {
            const float d0 = dbase[pix];
            const float d1 = dbase[pix + HWSZ];
            const float pt = t ? d1 : d0;
            const float lp = __logf(pt + EPSF);
            a_lp2 -= lp;
            a_ea2 -= lp * at;
            a_I2  += d1 * tf;
            a_U2  += d1;
        }
        a_T += tf;
    }

    // Block reduction of 13 values
    float vals[13] = { a_lp0, a_lp1, a_lp2,
                       a_ea0, a_ea1, a_ea2,
                       a_I0,  a_I1,  a_I2,
                       a_U0,  a_U1,  a_U2,
                       a_T };

    __shared__ float red[13][8];
    const int lane = threadIdx.x & 31;
    const int wrp  = threadIdx.x >> 5;
#pragma unroll
    for (int k = 0; k < 13; k++) {
        float v = vals[k];
#pragma unroll
        for (int o = 16; o > 0; o >>= 1)
            v += __shfl_down_sync(0xFFFFFFFFu, v, o);
        if (lane == 0) red[k][wrp] = v;
    }
    __syncthreads();

    if (threadIdx.x < 13) {
        const int k = threadIdx.x;
        double s = 0.0;
#pragma unroll
        for (int q = 0; q < 8; q++) s += (double)red[k][q];
        if (k < 3)        atomicAdd(&g_lp[k], s);
        else if (k < 6)   atomicAdd(&g_lpat[k - 3], s);
        else if (k < 9)   atomicAdd(&g_I[(k - 6) * 8 + b], s);
        else if (k < 12)  atomicAdd(&g_Up[(k - 9) * 8 + b], s);
        else              atomicAdd(&g_T[b], s);
    }
}

__global__ void finalize_kernel(const float* __restrict__ diffp,
                                const float* __restrict__ sigmap,
                                float* __restrict__ out)
{
    const double invBHW = 1.0 / ((double)BB * (double)HWSZ);
    const double s0 = (double)sigmap[0] * (double)sigmap[0];
    const double s1 = (double)sigmap[1] * (double)sigmap[1];
    const double s2 = (double)sigmap[2] * (double)sigmap[2];

    double loss = 0.0;
    for (int k = 0; k < 3; k++) {
        // focal
        loss += (g_lp[k] * invBHW) / s0;
        // dice
        double dm = 0.0;
        for (int b = 0; b < BB; b++) {
            const double U = g_Up[k * 8 + b] + g_T[b] + 1e-10;
            dm += 2.0 * g_I[k * 8 + b] / U;
        }
        loss += (1.0 - dm / (double)BB) / s1;
        // edge
        loss += (g_lpat[k] * invBHW) / s2;
    }
    loss += (double)diffp[0];
    loss += 0.5 * (log(s0) + log(s1) + log(s2));
    out[0] = (float)loss;
}

extern "C" void kernel_launch(void* const* d_in, const int* in_sizes, int n_in,
                              void* d_out, int out_size)
{
    const float* pred   = (const float*)d_in[0];  // (2, 8, 2, 1024, 1024)
    const float* diss   = (const float*)d_in[1];  // (1, 8, 2, 1024, 1024)
    const int*   target = (const int*)  d_in[2];  // (8, 1024, 1024)
    const float* diffp  = (const float*)d_in[3];  // scalar
    const float* sigmap = (const float*)d_in[4];  // (3,)
    float* out = (float*)d_out;

    zero_acc_kernel<<<1, 32>>>();

    dim3 grid(WW / 256, HH / 8, BB);
    dim3 block(256);
    combine_loss_main<<<grid, block>>>(pred, diss, target);

    finalize_kernel<<<1, 1>>>(diffp, sigmap, out);
}

// round 11
// speedup vs baseline: 1.0519x; 1.0519x over previous
#include <cuda_runtime.h>
#include <math.h>

#define WW 1024
#define HH 1024
#define BB 8
#define HWSZ (1024*1024)
#define EPSF 1e-10f

// Global accumulators. Zero-initialized at module load; finalize_kernel
// re-zeroes them after reading, so every kernel_launch call sees zeros.
// Layout: lp[3] @0, lpat[3] @3, I[3*8] @6, Up[3*8] @30, T[8] @54
__device__ double g_acc[62];

// Each thread: 4-wide (float4/int4 aligned) x 8-tall micro-tile.
// Block = 256 threads covering the full 1024-pixel row width.
// Grid = (1, H/8, B).
// 7x7 circular conv (29 taps, weight 1/29) over zero-padded target, built
// from per-row horizontal window sums (widths 7/5/5/5/5 and 1 for |dy|=3),
// packed 4 pixels per u32 (counts <= 29 fit in a byte).
__global__ __launch_bounds__(256, 2)
void combine_loss_main(const float* __restrict__ pred,
                       const float* __restrict__ diss,
                       const int*   __restrict__ target)
{
    const int b   = blockIdx.z;
    const int tid = threadIdx.x;
    const int c0  = tid << 2;          // leftmost of this thread's 4 columns
    const int h0  = blockIdx.y << 3;   // top row of this thread's 8 rows

    const int* __restrict__ tb = target + (size_t)b * HWSZ;

    unsigned cnt_p[8];   // packed conv counts, byte p = pixel column c0+p
    unsigned ctr_p[8];   // packed center target values
#pragma unroll
    for (int j = 0; j < 8; j++) cnt_p[j] = 0u;

#pragma unroll
    for (int a = 0; a < 14; a++) {
        const int r = h0 - 3 + a;
        int4 A = make_int4(0,0,0,0), B = A, C = A;
        if ((unsigned)r < (unsigned)HH) {
            const int* row = tb + (size_t)r * WW + c0;
            B = *(const int4*)row;                       // cols c0..c0+3
            if (c0 != 0)      A = *(const int4*)(row - 4); // cols c0-4..c0-1
            if (c0 != WW - 4) C = *(const int4*)(row + 4); // cols c0+4..c0+7
        }
        // t[i] covers column c0-4+i; values are 0/1
        const int t0=A.x, t1=A.y, t2=A.z, t3=A.w;
        const int t4=B.x, t5=B.y, t6=B.z, t7=B.w;
        const int t8=C.x, t9=C.y, t10=C.z;
        // prefix sums ps_i = t0+...+t_i
        const int ps1=t0+t1, ps2=ps1+t2, ps3=ps2+t3, ps4=ps3+t4, ps5=ps4+t5,
                  ps6=ps5+t6, ps7=ps6+t7, ps8=ps7+t8, ps9=ps8+t9, ps10=ps9+t10;
        // pixel p center at t[4+p]; 7-window = t[p+1..p+7]; 5-window = t[p+2..p+6]
        const unsigned s7 = (unsigned)(ps7 - t0)
                          | ((unsigned)(ps8 - ps1) << 8)
                          | ((unsigned)(ps9 - ps2) << 16)
                          | ((unsigned)(ps10 - ps3) << 24);
        const unsigned s5 = (unsigned)(ps6 - ps1)
                          | ((unsigned)(ps7 - ps2) << 8)
                          | ((unsigned)(ps8 - ps3) << 16)
                          | ((unsigned)(ps9 - ps4) << 24);
        const unsigned s1 = (unsigned)t4 | ((unsigned)t5 << 8)
                          | ((unsigned)t6 << 16) | ((unsigned)t7 << 24);

        // row a (abs row h0-3+a) contributes to output row j = (a-3) - dy:
        //   dy=0 -> s7 at j=a-3;  |dy|=1,2 -> s5 at j=a-1,a-2,a-4,a-5;
        //   |dy|=3 -> s1 at j=a, a-6
        if (a >= 3 && a <= 10) { cnt_p[a-3] += s7; ctr_p[a-3] = s1; }
        if (a >= 1 && a <= 8)  cnt_p[a-1] += s5;
        if (a >= 2 && a <= 9)  cnt_p[a-2] += s5;
        if (a >= 4 && a <= 11) cnt_p[a-4] += s5;
        if (a >= 5 && a <= 12) cnt_p[a-5] += s5;
        if (a <= 7)            cnt_p[a]   += s1;
        if (a >= 6)            cnt_p[a-6] += s1;
    }

    // acc: 0-2 lp, 3-5 lp*at, 6-8 I, 9-11 sum(p1), 12 sum(t)
    float acc[13];
#pragma unroll
    for (int k = 0; k < 13; k++) acc[k] = 0.f;

    const float* __restrict__ p0 = pred + (size_t)(b * 2) * HWSZ;         // i=0
    const float* __restrict__ p1 = pred + (size_t)((BB + b) * 2) * HWSZ;  // i=1
    const float* __restrict__ dd = diss + (size_t)(b * 2) * HWSZ;         // j=0
    const size_t base = (size_t)h0 * WW + c0;

#pragma unroll
    for (int j = 0; j < 8; j++) {
        const size_t pix = base + (size_t)j * WW;
        const float4 a0 = __ldcs((const float4*)(p0 + pix));
        const float4 a1 = __ldcs((const float4*)(p0 + pix + HWSZ));
        const float4 b0 = __ldcs((const float4*)(p1 + pix));
        const float4 b1 = __ldcs((const float4*)(p1 + pix + HWSZ));
        const float4 e0 = __ldcs((const float4*)(dd + pix));
        const float4 e1 = __ldcs((const float4*)(dd + pix + HWSZ));
        const float A0[4] = {a0.x, a0.y, a0.z, a0.w};
        const float A1[4] = {a1.x, a1.y, a1.z, a1.w};
        const float B0[4] = {b0.x, b0.y, b0.z, b0.w};
        const float B1[4] = {b1.x, b1.y, b1.z, b1.w};
        const float E0[4] = {e0.x, e0.y, e0.z, e0.w};
        const float E1[4] = {e1.x, e1.y, e1.z, e1.w};
        const unsigned cp = cnt_p[j], tp = ctr_p[j];

#pragma unroll
        for (int p = 0; p < 4; p++) {
            const int   ti  = (int)((tp >> (8 * p)) & 255u);
            const int   cnt = (int)((cp >> (8 * p)) & 255u);
            const float tf  = (float)ti;
            const float at  = fabsf(tf - (float)cnt * (1.0f / 29.0f));

            // tensor 0: softmax(pred[0]) as sigmoid
            {
                const float e  = __expf(A0[p] - A1[p]);
                const float q  = __fdividef(1.0f, 1.0f + e);  // p1
                const float pt = ti ? q : e * q;              // exact p0 = e*p1
                const float lp = __logf(pt + EPSF);
                acc[0] -= lp; acc[3] -= lp * at; acc[6] += q * tf; acc[9] += q;
            }
            // tensor 1: softmax(pred[1])
            {
                const float e  = __expf(B0[p] - B1[p]);
                const float q  = __fdividef(1.0f, 1.0f + e);
                const float pt = ti ? q : e * q;
                const float lp = __logf(pt + EPSF);
                acc[1] -= lp; acc[4] -= lp * at; acc[7] += q * tf; acc[10] += q;
            }
            // tensor 2: Diss used directly
            {
                const float pt = ti ? E1[p] : E0[p];
                const float lp = __logf(pt + EPSF);
                acc[2] -= lp; acc[5] -= lp * at; acc[8] += E1[p] * tf; acc[11] += E1[p];
            }
            acc[12] += tf;
        }
    }

    // Block reduction of 13 values, then double atomics (62 addresses total).
    __shared__ float red[13][8];
    const int lane = threadIdx.x & 31;
    const int wrp  = threadIdx.x >> 5;
#pragma unroll
    for (int k = 0; k < 13; k++) {
        float v = acc[k];
#pragma unroll
        for (int o = 16; o > 0; o >>= 1)
            v += __shfl_down_sync(0xFFFFFFFFu, v, o);
        if (lane == 0) red[k][wrp] = v;
    }
    __syncthreads();

    if (threadIdx.x < 13) {
        const int k = threadIdx.x;
        double s = 0.0;
#pragma unroll
        for (int q = 0; q < 8; q++) s += (double)red[k][q];
        int idx;
        if (k < 6)        idx = k;                      // lp[0..2], lpat[0..2]
        else if (k < 9)   idx = 6  + (k - 6) * 8 + b;   // I
        else if (k < 12)  idx = 30 + (k - 9) * 8 + b;   // Up
        else              idx = 54 + b;                 // T
        atomicAdd(&g_acc[idx], s);
    }
}

__global__ void finalize_kernel(const float* __restrict__ diffp,
                                const float* __restrict__ sigmap,
                                float* __restrict__ out)
{
    __shared__ double v[62];
    const int i = threadIdx.x;
    if (i < 62) v[i] = g_acc[i];
    __syncthreads();
    if (i < 62) g_acc[i] = 0.0;   // reset for the next launch (graph replay)

    if (i == 0) {
        const double invBHW = 1.0 / ((double)BB * (double)HWSZ);
        const double s0 = (double)sigmap[0] * (double)sigmap[0];
        const double s1 = (double)sigmap[1] * (double)sigmap[1];
        const double s2 = (double)sigmap[2] * (double)sigmap[2];

        double loss = 0.0;
        for (int k = 0; k < 3; k++) {
            loss += (v[k] * invBHW) / s0;               // focal
            double dm = 0.0;
            for (int b = 0; b < BB; b++) {
                const double U = v[30 + k * 8 + b] + v[54 + b] + 1e-10;
                dm += 2.0 * v[6 + k * 8 + b] / U;
            }
            loss += (1.0 - dm / (double)BB) / s1;       // dice
            loss += (v[3 + k] * invBHW) / s2;           // edge
        }
        loss += (double)diffp[0];
        loss += 0.5 * (log(s0) + log(s1) + log(s2));
        out[0] = (float)loss;
    }
}

extern "C" void kernel_launch(void* const* d_in, const int* in_sizes, int n_in,
                              void* d_out, int out_size)
{
    const float* pred   = (const float*)d_in[0];  // (2, 8, 2, 1024, 1024)
    const float* diss   = (const float*)d_in[1];  // (1, 8, 2, 1024, 1024)
    const int*   target = (const int*)  d_in[2];  // (8, 1024, 1024)
    const float* diffp  = (const float*)d_in[3];  // scalar
    const float* sigmap = (const float*)d_in[4];  // (3,)
    float* out = (float*)d_out;

    dim3 grid(1, HH / 8, BB);
    combine_loss_main<<<grid, 256>>>(pred, diss, target);
    finalize_kernel<<<1, 64>>>(diffp, sigmap, out);
}

// round 12
// speedup vs baseline: 1.3166x; 1.2517x over previous
#include <cuda_runtime.h>
#include <math.h>

#define WW 1024
#define HH 1024
#define BB 8
#define HWSZ (1024*1024)
#define EPSF 1e-10f

// Global accumulators. Zero-initialized at module load; finalize_kernel
// re-zeroes them after reading, so every kernel_launch call sees zeros.
// Layout: lp[3] @0, lpat[3] @3, I[3*8] @6, Up[3*8] @30, T[8] @54
__device__ double g_acc[62];

// Each thread: 4-wide (float4/int4 aligned) x 8-tall micro-tile.
// Block = 256 threads covering the full 1024-pixel row width.
// Grid = (1, H/8, B).
// 7x7 circular conv (29 taps, weight 1/29) over zero-padded target, built
// from per-row horizontal window sums (widths 7/5/5/5/5 and 1 for |dy|=3),
// packed 4 pixels per u32 (counts <= 29 fit in a byte).
__global__ __launch_bounds__(256, 2)
void combine_loss_main(const float* __restrict__ pred,
                       const float* __restrict__ diss,
                       const int*   __restrict__ target)
{
    const int b   = blockIdx.z;
    const int tid = threadIdx.x;
    const int c0  = tid << 2;          // leftmost of this thread's 4 columns
    const int h0  = blockIdx.y << 3;   // top row of this thread's 8 rows

    const int* __restrict__ tb = target + (size_t)b * HWSZ;

    unsigned cnt_p[8];   // packed conv counts, byte p = pixel column c0+p
    unsigned ctr_p[8];   // packed center target values
#pragma unroll
    for (int j = 0; j < 8; j++) cnt_p[j] = 0u;

#pragma unroll
    for (int a = 0; a < 14; a++) {
        const int r = h0 - 3 + a;
        int4 A = make_int4(0,0,0,0), B = A, C = A;
        if ((unsigned)r < (unsigned)HH) {
            const int* row = tb + (size_t)r * WW + c0;
            B = *(const int4*)row;                         // cols c0..c0+3
            if (c0 != 0)      A = *(const int4*)(row - 4); // cols c0-4..c0-1
            if (c0 != WW - 4) C = *(const int4*)(row + 4); // cols c0+4..c0+7
        }
        // t[i] covers column c0-4+i; values are 0/1
        const int t0=A.x, t1=A.y, t2=A.z, t3=A.w;
        const int t4=B.x, t5=B.y, t6=B.z, t7=B.w;
        const int t8=C.x, t9=C.y, t10=C.z;
        // prefix sums ps_i = t0+...+t_i
        const int ps1=t0+t1, ps2=ps1+t2, ps3=ps2+t3, ps4=ps3+t4, ps5=ps4+t5,
                  ps6=ps5+t6, ps7=ps6+t7, ps8=ps7+t8, ps9=ps8+t9, ps10=ps9+t10;
        // pixel p center at t[4+p]; 7-window = t[p+1..p+7]; 5-window = t[p+2..p+6]
        const unsigned s7 = (unsigned)(ps7 - t0)
                          | ((unsigned)(ps8 - ps1) << 8)
                          | ((unsigned)(ps9 - ps2) << 16)
                          | ((unsigned)(ps10 - ps3) << 24);
        const unsigned s5 = (unsigned)(ps6 - ps1)
                          | ((unsigned)(ps7 - ps2) << 8)
                          | ((unsigned)(ps8 - ps3) << 16)
                          | ((unsigned)(ps9 - ps4) << 24);
        const unsigned s1 = (unsigned)t4 | ((unsigned)t5 << 8)
                          | ((unsigned)t6 << 16) | ((unsigned)t7 << 24);

        // row a (abs row h0-3+a) contributes to output row j = (a-3) - dy:
        //   dy=0 -> s7 at j=a-3;  |dy|=1,2 -> s5 at j=a-1,a-2,a-4,a-5;
        //   |dy|=3 -> s1 at j=a, a-6
        if (a >= 3 && a <= 10) { cnt_p[a-3] += s7; ctr_p[a-3] = s1; }
        if (a >= 1 && a <= 8)  cnt_p[a-1] += s5;
        if (a >= 2 && a <= 9)  cnt_p[a-2] += s5;
        if (a >= 4 && a <= 11) cnt_p[a-4] += s5;
        if (a >= 5 && a <= 12) cnt_p[a-5] += s5;
        if (a <= 7)            cnt_p[a]   += s1;
        if (a >= 6)            cnt_p[a-6] += s1;
    }

    // acc: 0-2 lp, 3-5 lp*at, 6-8 I, 9-11 sum(p1), 12 sum(t)
    float acc[13];
#pragma unroll
    for (int k = 0; k < 13; k++) acc[k] = 0.f;

    const size_t base = (size_t)h0 * WW + c0;
    const float* __restrict__ p0a = pred + (size_t)(b * 2) * HWSZ + base;
    const float* __restrict__ p0b = p0a + HWSZ;
    const float* __restrict__ p1a = pred + (size_t)((BB + b) * 2) * HWSZ + base;
    const float* __restrict__ p1b = p1a + HWSZ;
    const float* __restrict__ dda = diss + (size_t)(b * 2) * HWSZ + base;
    const float* __restrict__ ddb = dda + HWSZ;

#pragma unroll
    for (int j = 0; j < 8; j++) {
        const size_t off = (size_t)j * WW;
        const float4 a0 = __ldcs((const float4*)(p0a + off));
        const float4 a1 = __ldcs((const float4*)(p0b + off));
        const float4 b0 = __ldcs((const float4*)(p1a + off));
        const float4 b1 = __ldcs((const float4*)(p1b + off));
        const float4 e0 = __ldcs((const float4*)(dda + off));
        const float4 e1 = __ldcs((const float4*)(ddb + off));
        const float A0[4] = {a0.x, a0.y, a0.z, a0.w};
        const float A1[4] = {a1.x, a1.y, a1.z, a1.w};
        const float B0[4] = {b0.x, b0.y, b0.z, b0.w};
        const float B1[4] = {b1.x, b1.y, b1.z, b1.w};
        const float E0[4] = {e0.x, e0.y, e0.z, e0.w};
        const float E1[4] = {e1.x, e1.y, e1.z, e1.w};
        const unsigned cp = cnt_p[j], tp = ctr_p[j];

#pragma unroll
        for (int p = 0; p < 4; p++) {
            const int   ti  = (int)((tp >> (8 * p)) & 255u);
            const int   cnt = (int)((cp >> (8 * p)) & 255u);
            const float tf  = (float)ti;
            const float at  = fabsf(tf - (float)cnt * (1.0f / 29.0f));

            // tensor 0: softmax(pred[0]) as sigmoid
            {
                const float e  = __expf(A0[p] - A1[p]);
                const float q  = __fdividef(1.0f, 1.0f + e);  // p1
                const float pt = ti ? q : e * q;              // exact p0 = e*p1
                const float lp = __logf(pt + EPSF);
                acc[0] -= lp; acc[3] -= lp * at; acc[6] += q * tf; acc[9] += q;
            }
            // tensor 1: softmax(pred[1])
            {
                const float e  = __expf(B0[p] - B1[p]);
                const float q  = __fdividef(1.0f, 1.0f + e);
                const float pt = ti ? q : e * q;
                const float lp = __logf(pt + EPSF);
                acc[1] -= lp; acc[4] -= lp * at; acc[7] += q * tf; acc[10] += q;
            }
            // tensor 2: Diss used directly
            {
                const float pt = ti ? E1[p] : E0[p];
                const float lp = __logf(pt + EPSF);
                acc[2] -= lp; acc[5] -= lp * at; acc[8] += E1[p] * tf; acc[11] += E1[p];
            }
            acc[12] += tf;
        }
    }

    // Block reduction of 13 values, then double atomics (62 addresses total).
    __shared__ float red[13][8];
    const int lane = threadIdx.x & 31;
    const int wrp  = threadIdx.x >> 5;
#pragma unroll
    for (int k = 0; k < 13; k++) {
        float v = acc[k];
#pragma unroll
        for (int o = 16; o > 0; o >>= 1)
            v += __shfl_down_sync(0xFFFFFFFFu, v, o);
        if (lane == 0) red[k][wrp] = v;
    }
    __syncthreads();

    if (threadIdx.x < 13) {
        const int k = threadIdx.x;
        double s = 0.0;
#pragma unroll
        for (int q = 0; q < 8; q++) s += (double)red[k][q];
        int idx;
        if (k < 6)        idx = k;                      // lp[0..2], lpat[0..2]
        else if (k < 9)   idx = 6  + (k - 6) * 8 + b;   // I
        else if (k < 12)  idx = 30 + (k - 9) * 8 + b;   // Up
        else              idx = 54 + b;                 // T
        atomicAdd(&g_acc[idx], s);
    }
}

// Parallel finalize: the 24 independent dice divisions go to 24 threads
// (FP64 div latency overlapped); the three 1/sigma^2 reciprocals go to 3
// threads. Serial FP64-div depth per thread is 1 (was ~27 in thread 0).
__global__ void finalize_kernel(const float* __restrict__ diffp,
                                const float* __restrict__ sigmap,
                                float* __restrict__ out)
{
    __shared__ double v[62];
    __shared__ double inv_s[3];
    __shared__ double dice_sum;
    const int i = threadIdx.x;

    if (i < 62) v[i] = g_acc[i];
    if (i < 3) {
        const double s = (double)sigmap[i] * (double)sigmap[i];
        inv_s[i] = 1.0 / s;   // independent FP64 divides, 3 threads in parallel
    }
    __syncthreads();
    if (i < 62) g_acc[i] = 0.0;   // reset for the next graph replay

    // Dice: 24 independent divisions in 24 threads of warp 0, shuffle-reduce.
    {
        double d = 0.0;
        if (i < 24) {
            const int k = i >> 3, bb = i & 7;
            const double U = v[30 + k * 8 + bb] + v[54 + bb] + 1e-10;
            d = 2.0 * v[6 + k * 8 + bb] / U;
        }
        if (i < 32) {
#pragma unroll
            for (int o = 16; o > 0; o >>= 1)
                d += __shfl_down_sync(0xFFFFFFFFu, d, o);
            if (i == 0) dice_sum = d;
        }
    }
    __syncthreads();

    if (i == 0) {
        const double invBHW = 1.0 / ((double)BB * (double)HWSZ);
        double loss = 0.0;
        // focal + edge: multiply by reciprocals (no divides)
        loss += (v[0] + v[1] + v[2]) * invBHW * inv_s[0];
        loss += (v[3] + v[4] + v[5]) * invBHW * inv_s[2];
        // dice: 3*(1 - mean) = 3 - dice_sum/BB, scaled by 1/s1
        loss += (3.0 - dice_sum * (1.0 / (double)BB)) * inv_s[1];
        loss += (double)diffp[0];
        // sum(log(sigma^2))/2 = -sum(log(1/sigma^2))/2
        loss -= 0.5 * (log(inv_s[0]) + log(inv_s[1]) + log(inv_s[2]));
        out[0] = (float)loss;
    }
}

extern "C" void kernel_launch(void* const* d_in, const int* in_sizes, int n_in,
                              void* d_out, int out_size)
{
    const float* pred   = (const float*)d_in[0];  // (2, 8, 2, 1024, 1024)
    const float* diss   = (const float*)d_in[1];  // (1, 8, 2, 1024, 1024)
    const int*   target = (const int*)  d_in[2];  // (8, 1024, 1024)
    const float* diffp  = (const float*)d_in[3];  // scalar
    const float* sigmap = (const float*)d_in[4];  // (3,)
    float* out = (float*)d_out;

    dim3 grid(1, HH / 8, BB);
    combine_loss_main<<<grid, 256>>>(pred, diss, target);
    finalize_kernel<<<1, 64>>>(diffp, sigmap, out);
}